// round 6
// baseline (speedup 1.0000x reference)
#include <cuda_runtime.h>
#include <cuda_bf16.h>
#include <math.h>
#include <stdint.h>

#define BB 8
#define NQ 2048
#define NK 2048
#define DD 256
#define MP 1152              // padded half-row count (9 * 128), rows 0..1024 real
typedef __nv_bfloat16 bf16;

// ---------------- static gmem scratch ----------------
__device__ bf16 g_CH[MP * 1024],      g_CL[MP * 1024];       // folded cos matrix
__device__ bf16 g_qH[BB * NQ * DD],   g_qL[BB * NQ * DD];
__device__ bf16 g_kH[BB * NK * DD],   g_kL[BB * NK * DD];
__device__ bf16 g_wqH[DD * DD],       g_wqL[DD * DD];
__device__ bf16 g_wkH[DD * DD],       g_wkL[DD * DD];
__device__ bf16 g_qpTH[DD * BB * NQ], g_qpTL[DD * BB * NQ];  // qprojT [256][16384]
__device__ bf16 g_qpFH[DD * BB * 1024], g_qpFL[DD * BB * 1024]; // folded qprojT
__device__ float g_q1024[BB * DD];                            // qproj row 1024
__device__ bf16 g_kpH[BB * NK * DD],  g_kpL[BB * NK * DD];   // kproj
__device__ bf16 g_qfH[BB * MP * DD],  g_qfL[BB * MP * DD];   // qfft (half rows)
__device__ bf16 g_vTH[BB * DD * NK],  g_vTL[BB * DD * NK];   // key^T (value)
__device__ float g_scores[(size_t)BB * MP * NK];
__device__ bf16 g_pH[(size_t)BB * MP * NK], g_pL[(size_t)BB * MP * NK];
__device__ float g_op[16 * MP * DD];                          // split-K partials

// ---------------- helpers ----------------
__device__ __forceinline__ unsigned smem_u32(const void* p) {
    unsigned a;
    asm("{ .reg .u64 t; cvta.to.shared.u64 t, %1; cvt.u32.u64 %0, t; }"
        : "=r"(a) : "l"(p));
    return a;
}
__device__ __forceinline__ void ldsm4(unsigned r[4], unsigned addr) {
    asm volatile("ldmatrix.sync.aligned.m8n8.x4.shared.b16 {%0,%1,%2,%3}, [%4];"
                 : "=r"(r[0]), "=r"(r[1]), "=r"(r[2]), "=r"(r[3]) : "r"(addr));
}
__device__ __forceinline__ void mma16816(float d[4], const unsigned a[4],
                                         unsigned b0, unsigned b1) {
    asm volatile(
        "mma.sync.aligned.m16n8k16.row.col.f32.bf16.bf16.f32 "
        "{%0,%1,%2,%3}, {%4,%5,%6,%7}, {%8,%9}, {%0,%1,%2,%3};"
        : "+f"(d[0]), "+f"(d[1]), "+f"(d[2]), "+f"(d[3])
        : "r"(a[0]), "r"(a[1]), "r"(a[2]), "r"(a[3]), "r"(b0), "r"(b1));
}
__device__ __forceinline__ void cpa(unsigned dst, const void* src) {
    asm volatile("cp.async.cg.shared.global [%0], [%1], 16;" :: "r"(dst), "l"(src));
}

// smem: 3 stages x 64KB; stage: Ah 0 | Al 16K | Bh 32K | Bl 48K. 128B rows.
#define SM_BYTES (3 * 65536)

// ---------------- prep kernels ----------------
__global__ void split_kernel(const float* __restrict__ x, bf16* __restrict__ h,
                             bf16* __restrict__ l, int n) {
    int i = blockIdx.x * blockDim.x + threadIdx.x;
    if (i < n) {
        float v = x[i];
        bf16 hv = __float2bfloat16(v);
        h[i] = hv;
        l[i] = __float2bfloat16(v - __bfloat162float(hv));
    }
}

__global__ void cinit_kernel() {   // C[m][k], m<MP, k<1024
    int i = blockIdx.x * blockDim.x + threadIdx.x;
    if (i < MP * 1024) {
        int m = i >> 10, k = i & 1023;
        float c = cospif((float)((m * k) & 2047) * (1.0f / 1024.0f));
        bf16 h = __float2bfloat16(c);
        g_CH[i] = h;
        g_CL[i] = __float2bfloat16(c - __bfloat162float(h));
    }
}

__global__ void transpose_kernel(const float* __restrict__ key,
                                 bf16* __restrict__ oH, bf16* __restrict__ oL) {
    __shared__ float ts[32][33];
    int b = blockIdx.z, n0 = blockIdx.x * 32, d0 = blockIdx.y * 32;
    const float* kb = key + (size_t)b * NK * DD;
#pragma unroll
    for (int i = 0; i < 4; i++) {
        int r = threadIdx.y + i * 8;
        ts[r][threadIdx.x] = kb[(size_t)(n0 + r) * DD + d0 + threadIdx.x];
    }
    __syncthreads();
#pragma unroll
    for (int i = 0; i < 4; i++) {
        int d = threadIdx.y + i * 8;
        float v = ts[threadIdx.x][d];
        size_t off = (size_t)b * DD * NK + (size_t)(d0 + d) * NK + n0 + threadIdx.x;
        bf16 h = __float2bfloat16(v);
        oH[off] = h;
        oL[off] = __float2bfloat16(v - __bfloat162float(h));
    }
}

// qpF[d][b*1024+k] = qpT[d][b*2048+k] (+ qpT[d][b*2048+2048-k] for k>0)
__global__ void fold_kernel() {
    int i = blockIdx.x * blockDim.x + threadIdx.x;
    if (i >= DD * BB * 1024) return;
    int d = i >> 13;
    int r = i & 8191;
    int b = r >> 10, k = r & 1023;
    size_t base = (size_t)d * (BB * NQ) + b * 2048;
    float v = __bfloat162float(g_qpTH[base + k]) + __bfloat162float(g_qpTL[base + k]);
    if (k > 0) {
        v += __bfloat162float(g_qpTH[base + 2048 - k]) +
             __bfloat162float(g_qpTL[base + 2048 - k]);
    }
    bf16 h = __float2bfloat16(v);
    g_qpFH[i] = h;
    g_qpFL[i] = __float2bfloat16(v - __bfloat162float(h));
}

__global__ void q1024_kernel() {
    int i = blockIdx.x * blockDim.x + threadIdx.x;
    if (i < BB * DD) {
        int b = i >> 8, d = i & 255;
        size_t off = (size_t)d * (BB * NQ) + b * 2048 + 1024;
        g_q1024[i] = __bfloat162float(g_qpTH[off]) + __bfloat162float(g_qpTL[off]);
    }
}

// ---------------------------------------------------------------------------
// Split-bf16 mma.sync GEMM, 3-stage cp.async pipeline + register-double-buffered
// fragments. D[m,n] = sum_k A[m,k]*B[n,k] (+bias[n]) (+(-1)^m fix[n]).
// CTA 128x128, kc=64, 256 thr, 8 warps 2m x 4n (warp 64x32).
// OUT: 0 fp32, 1 bf16 hi/lo. SPLITK: bz = b + 8*ks, operand k offset = ks*K.
// ---------------------------------------------------------------------------
template<int OUT, int FIX, int SPLITK>
__global__ void __launch_bounds__(256, 1)
gemm_kernel(const bf16* __restrict__ AH, const bf16* __restrict__ AL,
            size_t sA, int rA,
            const bf16* __restrict__ BH, const bf16* __restrict__ BL,
            size_t sB, int rB,
            const float* __restrict__ bias, const float* __restrict__ fix,
            float* __restrict__ D, bf16* __restrict__ DH, bf16* __restrict__ DL,
            size_t sD, int oS, int K)
{
    extern __shared__ char sm[];
    const unsigned smb = smem_u32(sm);
    const int tid = threadIdx.x;
    const int lane = tid & 31;
    const int wid = tid >> 5;
    const int m0 = blockIdx.y * 128;
    const int n0 = blockIdx.x * 128;
    const int bz = blockIdx.z;
    const int b  = SPLITK ? (bz & 7) : bz;
    const int koff = SPLITK ? (bz >> 3) * K : 0;
    const int wm = (wid & 1) * 64;
    const int wn = (wid >> 1) * 32;
    const int l15 = lane & 15;
    const int lh = lane >> 4;

    const bf16* AHb = AH + b * sA + koff;
    const bf16* ALb = AL + b * sA + koff;
    const bf16* BHb = BH + b * sB + koff;
    const bf16* BLb = BL + b * sB + koff;

    float acc[4][4][4];
#pragma unroll
    for (int t = 0; t < 4; t++)
#pragma unroll
        for (int j = 0; j < 4; j++)
#pragma unroll
            for (int i = 0; i < 4; i++) acc[t][j][i] = 0.0f;

    const int rw = tid >> 3, ch = tid & 7;

    // fa[pb][0..3]=A hi tiles, [4..7]=A lo; fb[pb][0..1]=B hi, [2..3]=B lo
    unsigned fa[2][8][4], fb[2][4][4];

    auto ISSUE = [&](int c) {
        const int ke = (c << 6) + ch * 8;
        const unsigned sb = smb + (c % 3) * 65536;
#pragma unroll
        for (int it = 0; it < 4; it++) {
            int r = rw + it * 32;
            unsigned so = sb + r * 128 + ((ch ^ (r & 7)) << 4);
            size_t go = (size_t)(m0 + r) * rA + ke;
            cpa(so, AHb + go);
            cpa(so + 16384, ALb + go);
        }
#pragma unroll
        for (int it = 0; it < 4; it++) {
            int r = rw + it * 32;
            unsigned so = sb + 32768 + r * 128 + ((ch ^ (r & 7)) << 4);
            size_t go = (size_t)(n0 + r) * rB + ke;
            cpa(so, BHb + go);
            cpa(so + 16384, BLb + go);
        }
        asm volatile("cp.async.commit_group;" ::: "memory");
    };

    auto LDF = [&](unsigned ab, int ks, int pb) {
#pragma unroll
        for (int t = 0; t < 4; t++) {
            int row = wm + 16 * t + l15;
            unsigned so = ab + row * 128 + (((ks * 2 + lh) ^ (row & 7)) << 4);
            ldsm4(fa[pb][t], so);
            ldsm4(fa[pb][4 + t], so + 16384);
        }
#pragma unroll
        for (int nt = 0; nt < 2; nt++) {
            int row = wn + 16 * nt + l15;
            unsigned so = ab + 32768 + row * 128 +
                          (((ks * 2 + lh) ^ (row & 7)) << 4);
            ldsm4(fb[pb][nt], so);
            ldsm4(fb[pb][2 + nt], so + 16384);
        }
    };

    auto MMAS = [&](int pb) {
        // pass 1: hi*hi
#pragma unroll
        for (int t = 0; t < 4; t++)
#pragma unroll
            for (int nt = 0; nt < 2; nt++)
#pragma unroll
                for (int s = 0; s < 2; s++)
                    mma16816(acc[t][nt * 2 + s], fa[pb][t],
                             fb[pb][nt][s], fb[pb][nt][2 + s]);
        // pass 2: hi*lo
#pragma unroll
        for (int t = 0; t < 4; t++)
#pragma unroll
            for (int nt = 0; nt < 2; nt++)
#pragma unroll
                for (int s = 0; s < 2; s++)
                    mma16816(acc[t][nt * 2 + s], fa[pb][t],
                             fb[pb][2 + nt][s], fb[pb][2 + nt][2 + s]);
        // pass 3: lo*hi
#pragma unroll
        for (int t = 0; t < 4; t++)
#pragma unroll
            for (int nt = 0; nt < 2; nt++)
#pragma unroll
                for (int s = 0; s < 2; s++)
                    mma16816(acc[t][nt * 2 + s], fa[pb][4 + t],
                             fb[pb][nt][s], fb[pb][nt][2 + s]);
    };

    const int NC = K >> 6;
    ISSUE(0);
    ISSUE(1);
#pragma unroll 1
    for (int c = 0; c < NC; c++) {
        if (c < NC - 1) asm volatile("cp.async.wait_group 1;" ::: "memory");
        else            asm volatile("cp.async.wait_group 0;" ::: "memory");
        __syncthreads();
        if (c + 2 < NC) ISSUE(c + 2);
        const unsigned ab = smb + (c % 3) * 65536;
        LDF(ab, 0, 0);
#pragma unroll
        for (int ks = 0; ks < 4; ks++) {
            if (ks < 3) LDF(ab, ks + 1, (ks + 1) & 1);
            MMAS(ks & 1);
        }
    }

    // ---- epilogue: direct frag stores ----
#pragma unroll
    for (int t = 0; t < 4; t++) {
#pragma unroll
        for (int j = 0; j < 4; j++) {
            int r0 = m0 + wm + 16 * t + (lane >> 2);
            int col = n0 + wn + 8 * j + 2 * (lane & 3);
            float b0v = 0.0f, b1v = 0.0f;
            if (bias) { b0v = __ldg(&bias[col]); b1v = __ldg(&bias[col + 1]); }
            if (FIX) {
                const float* fx = fix + b * DD;
                float sg = (r0 & 1) ? -1.0f : 1.0f;
                b0v += sg * __ldg(&fx[col]);
                b1v += sg * __ldg(&fx[col + 1]);
            }
            float v0 = acc[t][j][0] + b0v, v1 = acc[t][j][1] + b1v;
            float v2 = acc[t][j][2] + b0v, v3 = acc[t][j][3] + b1v;
            if (OUT == 0) {
                float* Dp = D + bz * sD;
                *(float2*)(Dp + (size_t)r0 * oS + col) = make_float2(v0, v1);
                *(float2*)(Dp + (size_t)(r0 + 8) * oS + col) = make_float2(v2, v3);
            } else {
                bf16* Hp = DH + bz * sD;
                bf16* Lp = DL + bz * sD;
                __nv_bfloat162 h01, h23, l01, l23;
                h01.x = __float2bfloat16(v0); h01.y = __float2bfloat16(v1);
                h23.x = __float2bfloat16(v2); h23.y = __float2bfloat16(v3);
                l01.x = __float2bfloat16(v0 - __bfloat162float(h01.x));
                l01.y = __float2bfloat16(v1 - __bfloat162float(h01.y));
                l23.x = __float2bfloat16(v2 - __bfloat162float(h23.x));
                l23.y = __float2bfloat16(v3 - __bfloat162float(h23.y));
                *(__nv_bfloat162*)(Hp + (size_t)r0 * oS + col) = h01;
                *(__nv_bfloat162*)(Lp + (size_t)r0 * oS + col) = l01;
                *(__nv_bfloat162*)(Hp + (size_t)(r0 + 8) * oS + col) = h23;
                *(__nv_bfloat162*)(Lp + (size_t)(r0 + 8) * oS + col) = l23;
            }
        }
    }
}

// ---------------------------------------------------------------------------
// Row softmax over NK with scale 1/16; emits probs as bf16 hi/lo
// ---------------------------------------------------------------------------
__global__ void softmax_kernel(const float* __restrict__ s,
                               bf16* __restrict__ pH, bf16* __restrict__ pL) {
    size_t row = blockIdx.x;
    const float* p = s + row * (size_t)NK;
    int t = threadIdx.x;
    float v[8];
#pragma unroll
    for (int i = 0; i < 8; i++) v[i] = p[t + 256 * i] * 0.0625f;
    float mx = v[0];
#pragma unroll
    for (int i = 1; i < 8; i++) mx = fmaxf(mx, v[i]);
#pragma unroll
    for (int o = 16; o > 0; o >>= 1) mx = fmaxf(mx, __shfl_xor_sync(0xffffffffu, mx, o));
    __shared__ float redm[8], reds[8];
    if ((t & 31) == 0) redm[t >> 5] = mx;
    __syncthreads();
    float m2 = redm[0];
#pragma unroll
    for (int i = 1; i < 8; i++) m2 = fmaxf(m2, redm[i]);
    float sum = 0.0f;
#pragma unroll
    for (int i = 0; i < 8; i++) { v[i] = __expf(v[i] - m2); sum += v[i]; }
#pragma unroll
    for (int o = 16; o > 0; o >>= 1) sum += __shfl_xor_sync(0xffffffffu, sum, o);
    if ((t & 31) == 0) reds[t >> 5] = sum;
    __syncthreads();
    float s2 = 0.0f;
#pragma unroll
    for (int i = 0; i < 8; i++) s2 += reds[i];
    float inv = 1.0f / s2;
    size_t base = row * (size_t)NK + t;
#pragma unroll
    for (int i = 0; i < 8; i++) {
        float pv = v[i] * inv;
        bf16 h = __float2bfloat16(pv);
        pH[base + 256 * i] = h;
        pL[base + 256 * i] = __float2bfloat16(pv - __bfloat162float(h));
    }
}

// ---------------------------------------------------------------------------
// combine split-K partials + mirror rows: out[b][m] = out[b][2048-m]
// ---------------------------------------------------------------------------
__global__ void combine_kernel(const float* __restrict__ op, float* __restrict__ out) {
    int m = blockIdx.x, b = blockIdx.y, d = threadIdx.x;
    size_t src = ((size_t)b * MP + m) * DD + d;
    float v = op[src] + op[src + (size_t)8 * MP * DD];
    out[((size_t)b * NQ + m) * DD + d] = v;
    if (m >= 1 && m <= 1023)
        out[((size_t)b * NQ + 2048 - m) * DD + d] = v;
}

// ---------------------------------------------------------------------------
extern "C" void kernel_launch(void* const* d_in, const int* in_sizes, int n_in,
                              void* d_out, int out_size) {
    const float* query = (const float*)d_in[0];
    const float* key   = (const float*)d_in[1];
    const float* Wq    = (const float*)d_in[2];
    const float* bq    = (const float*)d_in[3];
    const float* Wk    = (const float*)d_in[4];
    const float* bk    = (const float*)d_in[5];
    float* out = (float*)d_out;

#define SYM(p, s) void* p; cudaGetSymbolAddress(&p, s)
    SYM(qH, g_qH);   SYM(qL, g_qL);   SYM(kH, g_kH);   SYM(kL, g_kL);
    SYM(wqH, g_wqH); SYM(wqL, g_wqL); SYM(wkH, g_wkH); SYM(wkL, g_wkL);
    SYM(qpTH, g_qpTH); SYM(qpTL, g_qpTL);
    SYM(qpFH, g_qpFH); SYM(qpFL, g_qpFL);
    SYM(q1024, g_q1024);
    SYM(kpH, g_kpH); SYM(kpL, g_kpL);
    SYM(qfH, g_qfH); SYM(qfL, g_qfL);
    SYM(vTH, g_vTH); SYM(vTL, g_vTL);
    SYM(pH, g_pH);   SYM(pL, g_pL);
    SYM(CH, g_CH);   SYM(CL, g_CL);
    SYM(sc, g_scores); SYM(op, g_op);
#undef SYM

    cudaFuncSetAttribute((const void*)gemm_kernel<1,0,0>, cudaFuncAttributeMaxDynamicSharedMemorySize, SM_BYTES);
    cudaFuncSetAttribute((const void*)gemm_kernel<1,1,0>, cudaFuncAttributeMaxDynamicSharedMemorySize, SM_BYTES);
    cudaFuncSetAttribute((const void*)gemm_kernel<0,0,0>, cudaFuncAttributeMaxDynamicSharedMemorySize, SM_BYTES);
    cudaFuncSetAttribute((const void*)gemm_kernel<0,0,1>, cudaFuncAttributeMaxDynamicSharedMemorySize, SM_BYTES);

    // preps
    cinit_kernel<<<(MP * 1024 + 255) / 256, 256>>>();
    split_kernel<<<16384, 256>>>(query, (bf16*)qH, (bf16*)qL, BB * NQ * DD);
    split_kernel<<<16384, 256>>>(key,   (bf16*)kH, (bf16*)kL, BB * NK * DD);
    split_kernel<<<256, 256>>>(Wq, (bf16*)wqH, (bf16*)wqL, DD * DD);
    split_kernel<<<256, 256>>>(Wk, (bf16*)wkH, (bf16*)wkL, DD * DD);
    transpose_kernel<<<dim3(NK / 32, DD / 32, BB), dim3(32, 8)>>>(
        key, (bf16*)vTH, (bf16*)vTL);

    // G1: qprojT[d, b*m] = Wq @ query^T    (M=256, N=16384, K=256)
    gemm_kernel<1,0,0><<<dim3(128, 2, 1), 256, SM_BYTES>>>(
        (bf16*)wqH, (bf16*)wqL, 0, DD, (bf16*)qH, (bf16*)qL, 0, DD,
        nullptr, nullptr, nullptr, (bf16*)qpTH, (bf16*)qpTL, 0, BB * NQ, DD);
    // G2: kproj = key @ Wk^T + bk          (M=16384, N=256, K=256)
    gemm_kernel<1,0,0><<<dim3(2, 128, 1), 256, SM_BYTES>>>(
        (bf16*)kH, (bf16*)kL, 0, DD, (bf16*)wkH, (bf16*)wkL, 0, DD,
        bk, nullptr, nullptr, (bf16*)kpH, (bf16*)kpL, 0, DD, DD);

    // fold + row-1024 extraction (after G1)
    fold_kernel<<<(DD * BB * 1024 + 255) / 256, 256>>>();
    q1024_kernel<<<(BB * DD + 255) / 256, 256>>>();

    // G3: qfft = Cfold @ qpF^T + bq + (-1)^m q1024   (per b: M=1152, N=256, K=1024)
    gemm_kernel<1,1,0><<<dim3(2, 9, BB), 256, SM_BYTES>>>(
        (bf16*)CH, (bf16*)CL, 0, 1024, (bf16*)qpFH, (bf16*)qpFL, 1024, BB * 1024,
        bq, (const float*)q1024, nullptr, (bf16*)qfH, (bf16*)qfL,
        (size_t)MP * DD, DD, 1024);
    // G4: scores = qfft @ kproj^T          (per b: M=1152, N=2048, K=256)
    gemm_kernel<0,0,0><<<dim3(16, 9, BB), 256, SM_BYTES>>>(
        (bf16*)qfH, (bf16*)qfL, (size_t)MP * DD, DD,
        (bf16*)kpH, (bf16*)kpL, (size_t)NK * DD, DD,
        nullptr, nullptr, (float*)sc, nullptr, nullptr, (size_t)MP * NK, NK, DD);
    // softmax -> probs hi/lo
    softmax_kernel<<<BB * MP, 256>>>((float*)sc, (bf16*)pH, (bf16*)pL);
    // G5: partial out = probs @ vT^T, 2-way split-K  (per bz: M=1152, N=256, K=1024)
    gemm_kernel<0,0,1><<<dim3(2, 9, 16), 256, SM_BYTES>>>(
        (bf16*)pH, (bf16*)pL, (size_t)MP * NK, NK,
        (bf16*)vTH, (bf16*)vTL, (size_t)DD * NK, NK,
        nullptr, nullptr, (float*)op, nullptr, nullptr, (size_t)MP * DD, DD, 1024);
    // combine partials + mirror
    combine_kernel<<<dim3(1025, BB), 256>>>((const float*)op, out);
}

// round 7
// speedup vs baseline: 1.0176x; 1.0176x over previous
#include <cuda_runtime.h>
#include <cuda_bf16.h>
#include <math.h>
#include <stdint.h>

#define BB 8
#define NQ 2048
#define NK 2048
#define DD 256
#define MP 1152              // padded half-row count (9 * 128), rows 0..1024 real
typedef __nv_bfloat16 bf16;

// ---------------- static gmem scratch ----------------
__device__ bf16 g_CH[MP * 1024],      g_CL[MP * 1024];       // folded cos matrix
__device__ bf16 g_qH[BB * NQ * DD],   g_qL[BB * NQ * DD];
__device__ bf16 g_kH[BB * NK * DD],   g_kL[BB * NK * DD];
__device__ bf16 g_wqH[DD * DD],       g_wqL[DD * DD];
__device__ bf16 g_wkH[DD * DD],       g_wkL[DD * DD];
__device__ bf16 g_qpTH[DD * BB * NQ], g_qpTL[DD * BB * NQ];  // qprojT [256][16384]
__device__ bf16 g_qpFH[DD * BB * 1024], g_qpFL[DD * BB * 1024]; // folded qprojT
__device__ float g_q1024[BB * DD];                            // qproj row 1024
__device__ bf16 g_kpH[BB * NK * DD],  g_kpL[BB * NK * DD];   // kproj
__device__ bf16 g_qfH[BB * MP * DD],  g_qfL[BB * MP * DD];   // qfft (half rows)
__device__ bf16 g_vTH[BB * DD * NK],  g_vTL[BB * DD * NK];   // key^T (value)
__device__ float g_scores[(size_t)BB * MP * NK];
__device__ bf16 g_pH[(size_t)BB * MP * NK], g_pL[(size_t)BB * MP * NK];
__device__ float g_op[16 * MP * DD];                          // split-K partials

// ---------------- helpers ----------------
__device__ __forceinline__ unsigned smem_u32(const void* p) {
    unsigned a;
    asm("{ .reg .u64 t; cvta.to.shared.u64 t, %1; cvt.u32.u64 %0, t; }"
        : "=r"(a) : "l"(p));
    return a;
}
__device__ __forceinline__ void ldsm4(unsigned r[4], unsigned addr) {
    asm volatile("ldmatrix.sync.aligned.m8n8.x4.shared.b16 {%0,%1,%2,%3}, [%4];"
                 : "=r"(r[0]), "=r"(r[1]), "=r"(r[2]), "=r"(r[3]) : "r"(addr));
}
__device__ __forceinline__ void mma16816(float d[4], const unsigned a[4],
                                         unsigned b0, unsigned b1) {
    asm volatile(
        "mma.sync.aligned.m16n8k16.row.col.f32.bf16.bf16.f32 "
        "{%0,%1,%2,%3}, {%4,%5,%6,%7}, {%8,%9}, {%0,%1,%2,%3};"
        : "+f"(d[0]), "+f"(d[1]), "+f"(d[2]), "+f"(d[3])
        : "r"(a[0]), "r"(a[1]), "r"(a[2]), "r"(a[3]), "r"(b0), "r"(b1));
}
__device__ __forceinline__ void cpa(unsigned dst, const void* src) {
    asm volatile("cp.async.cg.shared.global [%0], [%1], 16;" :: "r"(dst), "l"(src));
}

// smem: 2 stages x 96KB; stage: Ah 0 | Al 16K | Bh 32K | Bl 64K. 128B rows, XOR8 swizzle.
#define SM_BYTES (2 * 98304)

// ---------------- prep kernels ----------------
__global__ void split_kernel(const float* __restrict__ x, bf16* __restrict__ h,
                             bf16* __restrict__ l, int n) {
    int i = blockIdx.x * blockDim.x + threadIdx.x;
    if (i < n) {
        float v = x[i];
        bf16 hv = __float2bfloat16(v);
        h[i] = hv;
        l[i] = __float2bfloat16(v - __bfloat162float(hv));
    }
}

__global__ void cinit_kernel() {   // C[m][k], m<MP, k<1024
    int i = blockIdx.x * blockDim.x + threadIdx.x;
    if (i < MP * 1024) {
        int m = i >> 10, k = i & 1023;
        float c = cospif((float)((m * k) & 2047) * (1.0f / 1024.0f));
        bf16 h = __float2bfloat16(c);
        g_CH[i] = h;
        g_CL[i] = __float2bfloat16(c - __bfloat162float(h));
    }
}

__global__ void transpose_kernel(const float* __restrict__ key,
                                 bf16* __restrict__ oH, bf16* __restrict__ oL) {
    __shared__ float ts[32][33];
    int b = blockIdx.z, n0 = blockIdx.x * 32, d0 = blockIdx.y * 32;
    const float* kb = key + (size_t)b * NK * DD;
#pragma unroll
    for (int i = 0; i < 4; i++) {
        int r = threadIdx.y + i * 8;
        ts[r][threadIdx.x] = kb[(size_t)(n0 + r) * DD + d0 + threadIdx.x];
    }
    __syncthreads();
#pragma unroll
    for (int i = 0; i < 4; i++) {
        int d = threadIdx.y + i * 8;
        float v = ts[threadIdx.x][d];
        size_t off = (size_t)b * DD * NK + (size_t)(d0 + d) * NK + n0 + threadIdx.x;
        bf16 h = __float2bfloat16(v);
        oH[off] = h;
        oL[off] = __float2bfloat16(v - __bfloat162float(h));
    }
}

// qpF[d][b*1024+k] = qpT[d][b*2048+k] (+ qpT[d][b*2048+2048-k] for k>0)
__global__ void fold_kernel() {
    int i = blockIdx.x * blockDim.x + threadIdx.x;
    if (i >= DD * BB * 1024) return;
    int d = i >> 13;
    int r = i & 8191;
    int b = r >> 10, k = r & 1023;
    size_t base = (size_t)d * (BB * NQ) + b * 2048;
    float v = __bfloat162float(g_qpTH[base + k]) + __bfloat162float(g_qpTL[base + k]);
    if (k > 0) {
        v += __bfloat162float(g_qpTH[base + 2048 - k]) +
             __bfloat162float(g_qpTL[base + 2048 - k]);
    }
    bf16 h = __float2bfloat16(v);
    g_qpFH[i] = h;
    g_qpFL[i] = __float2bfloat16(v - __bfloat162float(h));
}

__global__ void q1024_kernel() {
    int i = blockIdx.x * blockDim.x + threadIdx.x;
    if (i < BB * DD) {
        int b = i >> 8, d = i & 255;
        size_t off = (size_t)d * (BB * NQ) + b * 2048 + 1024;
        g_q1024[i] = __bfloat162float(g_qpTH[off]) + __bfloat162float(g_qpTL[off]);
    }
}

// ---------------------------------------------------------------------------
// Split-bf16 mma.sync GEMM.  D[m,n] = sum_k A[m,k]*B[n,k] (+bias[n]).
// CTA 128m x 256n, kc=64, 512 threads, 16 warps as 2m x 8n of 64x32 tiles.
// Pass-major MMA order; B hi/lo planes sequenced to cap register use.
// OUT: 0 fp32, 1 bf16 hi/lo.  SPLITK: bz = b + 8*ks, k offset = ks*K.
// ---------------------------------------------------------------------------
template<int OUT, int SPLITK>
__global__ void __launch_bounds__(512, 1)
gemm_kernel(const bf16* __restrict__ AH, const bf16* __restrict__ AL,
            size_t sA, int rA,
            const bf16* __restrict__ BH, const bf16* __restrict__ BL,
            size_t sB, int rB,
            const float* __restrict__ bias,
            float* __restrict__ D, bf16* __restrict__ DH, bf16* __restrict__ DL,
            size_t sD, int oS, int K)
{
    extern __shared__ char sm[];
    const unsigned smb = smem_u32(sm);
    const int tid = threadIdx.x;
    const int lane = tid & 31;
    const int wid = tid >> 5;
    const int m0 = blockIdx.y * 128;
    const int n0 = blockIdx.x * 256;
    const int bz = blockIdx.z;
    const int b  = SPLITK ? (bz & 7) : bz;
    const int koff = SPLITK ? (bz >> 3) * K : 0;
    const int wm = (wid & 1) * 64;
    const int wn = (wid >> 1) * 32;
    const int l15 = lane & 15;
    const int lh = lane >> 4;

    const bf16* AHb = AH + b * sA + koff;
    const bf16* ALb = AL + b * sA + koff;
    const bf16* BHb = BH + b * sB + koff;
    const bf16* BLb = BL + b * sB + koff;

    float acc[4][4][4];
#pragma unroll
    for (int t = 0; t < 4; t++)
#pragma unroll
        for (int j = 0; j < 4; j++)
#pragma unroll
            for (int i = 0; i < 4; i++) acc[t][j][i] = 0.0f;

    const int rw = tid >> 3, ch = tid & 7;   // 64 rows x 8 k-chunks per sweep

    auto ISSUE = [&](int c) {
        const int ke = (c << 6) + ch * 8;
        const unsigned sb = smb + (c & 1) * 98304;
#pragma unroll
        for (int it = 0; it < 2; it++) {
            int r = rw + it * 64;
            unsigned so = sb + r * 128 + ((ch ^ (r & 7)) << 4);
            size_t go = (size_t)(m0 + r) * rA + ke;
            cpa(so, AHb + go);
            cpa(so + 16384, ALb + go);
        }
#pragma unroll
        for (int it = 0; it < 4; it++) {
            int r = rw + it * 64;
            unsigned so = sb + 32768 + r * 128 + ((ch ^ (r & 7)) << 4);
            size_t go = (size_t)(n0 + r) * rB + ke;
            cpa(so, BHb + go);
            cpa(so + 32768, BLb + go);
        }
        asm volatile("cp.async.commit_group;" ::: "memory");
    };

    const int NC = K >> 6;
    ISSUE(0);
#pragma unroll 1
    for (int c = 0; c < NC; c++) {
        if (c + 1 < NC) {
            ISSUE(c + 1);
            asm volatile("cp.async.wait_group 1;" ::: "memory");
        } else {
            asm volatile("cp.async.wait_group 0;" ::: "memory");
        }
        __syncthreads();
        const unsigned ab = smb + (c & 1) * 98304;
#pragma unroll
        for (int ks = 0; ks < 4; ks++) {
            unsigned Ah[4][4], Al[4][4], Bp[2][4];
            const unsigned cc = (unsigned)(ks * 2 + lh);
#pragma unroll
            for (int t = 0; t < 4; t++) {
                int row = wm + 16 * t + l15;
                unsigned so = ab + row * 128 + ((cc ^ (row & 7)) << 4);
                ldsm4(Ah[t], so);
                ldsm4(Al[t], so + 16384);
            }
            // B hi plane
#pragma unroll
            for (int nt = 0; nt < 2; nt++) {
                int row = wn + 16 * nt + l15;
                unsigned so = ab + 32768 + row * 128 + ((cc ^ (row & 7)) << 4);
                ldsm4(Bp[nt], so);
            }
            // pass 1: hi*hi   (pass-major: 16 indep MMAs between acc reuses)
#pragma unroll
            for (int t = 0; t < 4; t++)
#pragma unroll
                for (int nt = 0; nt < 2; nt++)
#pragma unroll
                    for (int s = 0; s < 2; s++)
                        mma16816(acc[t][nt * 2 + s], Ah[t], Bp[nt][s], Bp[nt][2 + s]);
            // pass 2: lo*hi
#pragma unroll
            for (int t = 0; t < 4; t++)
#pragma unroll
                for (int nt = 0; nt < 2; nt++)
#pragma unroll
                    for (int s = 0; s < 2; s++)
                        mma16816(acc[t][nt * 2 + s], Al[t], Bp[nt][s], Bp[nt][2 + s]);
            // B lo plane (overwrites Bp)
#pragma unroll
            for (int nt = 0; nt < 2; nt++) {
                int row = wn + 16 * nt + l15;
                unsigned so = ab + 65536 + row * 128 + ((cc ^ (row & 7)) << 4);
                ldsm4(Bp[nt], so);
            }
            // pass 3: hi*lo
#pragma unroll
            for (int t = 0; t < 4; t++)
#pragma unroll
                for (int nt = 0; nt < 2; nt++)
#pragma unroll
                    for (int s = 0; s < 2; s++)
                        mma16816(acc[t][nt * 2 + s], Ah[t], Bp[nt][s], Bp[nt][2 + s]);
        }
        __syncthreads();
    }

    // ---- epilogue ----
#pragma unroll
    for (int t = 0; t < 4; t++) {
#pragma unroll
        for (int j = 0; j < 4; j++) {
            int r0 = m0 + wm + 16 * t + (lane >> 2);
            int col = n0 + wn + 8 * j + 2 * (lane & 3);
            float b0v = 0.0f, b1v = 0.0f;
            if (bias) { b0v = __ldg(&bias[col]); b1v = __ldg(&bias[col + 1]); }
            float v0 = acc[t][j][0] + b0v, v1 = acc[t][j][1] + b1v;
            float v2 = acc[t][j][2] + b0v, v3 = acc[t][j][3] + b1v;
            if (OUT == 0) {
                float* Dp = D + bz * sD;
                *(float2*)(Dp + (size_t)r0 * oS + col) = make_float2(v0, v1);
                *(float2*)(Dp + (size_t)(r0 + 8) * oS + col) = make_float2(v2, v3);
            } else {
                bf16* Hp = DH + bz * sD;
                bf16* Lp = DL + bz * sD;
                __nv_bfloat162 h01, h23, l01, l23;
                h01.x = __float2bfloat16(v0); h01.y = __float2bfloat16(v1);
                h23.x = __float2bfloat16(v2); h23.y = __float2bfloat16(v3);
                l01.x = __float2bfloat16(v0 - __bfloat162float(h01.x));
                l01.y = __float2bfloat16(v1 - __bfloat162float(h01.y));
                l23.x = __float2bfloat16(v2 - __bfloat162float(h23.x));
                l23.y = __float2bfloat16(v3 - __bfloat162float(h23.y));
                *(__nv_bfloat162*)(Hp + (size_t)r0 * oS + col) = h01;
                *(__nv_bfloat162*)(Lp + (size_t)r0 * oS + col) = l01;
                *(__nv_bfloat162*)(Hp + (size_t)(r0 + 8) * oS + col) = h23;
                *(__nv_bfloat162*)(Lp + (size_t)(r0 + 8) * oS + col) = l23;
            }
        }
    }
}

// ---------------------------------------------------------------------------
// Row softmax over NK with scale 1/16; emits probs as bf16 hi/lo
// ---------------------------------------------------------------------------
__global__ void softmax_kernel(const float* __restrict__ s,
                               bf16* __restrict__ pH, bf16* __restrict__ pL) {
    size_t row = blockIdx.x;
    const float* p = s + row * (size_t)NK;
    int t = threadIdx.x;
    float v[8];
#pragma unroll
    for (int i = 0; i < 8; i++) v[i] = p[t + 256 * i] * 0.0625f;
    float mx = v[0];
#pragma unroll
    for (int i = 1; i < 8; i++) mx = fmaxf(mx, v[i]);
#pragma unroll
    for (int o = 16; o > 0; o >>= 1) mx = fmaxf(mx, __shfl_xor_sync(0xffffffffu, mx, o));
    __shared__ float redm[8], reds[8];
    if ((t & 31) == 0) redm[t >> 5] = mx;
    __syncthreads();
    float m2 = redm[0];
#pragma unroll
    for (int i = 1; i < 8; i++) m2 = fmaxf(m2, redm[i]);
    float sum = 0.0f;
#pragma unroll
    for (int i = 0; i < 8; i++) { v[i] = __expf(v[i] - m2); sum += v[i]; }
#pragma unroll
    for (int o = 16; o > 0; o >>= 1) sum += __shfl_xor_sync(0xffffffffu, sum, o);
    if ((t & 31) == 0) reds[t >> 5] = sum;
    __syncthreads();
    float s2 = 0.0f;
#pragma unroll
    for (int i = 0; i < 8; i++) s2 += reds[i];
    float inv = 1.0f / s2;
    size_t base = row * (size_t)NK + t;
#pragma unroll
    for (int i = 0; i < 8; i++) {
        float pv = v[i] * inv;
        bf16 h = __float2bfloat16(pv);
        pH[base + 256 * i] = h;
        pL[base + 256 * i] = __float2bfloat16(pv - __bfloat162float(h));
    }
}

// ---------------------------------------------------------------------------
// G3 combine: qf = op_part0 + op_part1 + bq + (-1)^m q1024 -> bf16 hi/lo
// grid (MP, BB), 256 thr = d
// ---------------------------------------------------------------------------
__global__ void g3combine_kernel(const float* __restrict__ op,
                                 const float* __restrict__ bq) {
    int m = blockIdx.x, b = blockIdx.y, d = threadIdx.x;
    size_t idx = ((size_t)b * MP + m) * DD + d;
    float fx = g_q1024[b * DD + d];
    float v = op[idx] + op[idx + (size_t)8 * MP * DD] + bq[d] +
              ((m & 1) ? -fx : fx);
    bf16 h = __float2bfloat16(v);
    g_qfH[idx] = h;
    g_qfL[idx] = __float2bfloat16(v - __bfloat162float(h));
}

// ---------------------------------------------------------------------------
// final combine: split-K partials + mirror rows out[b][2048-m] = out[b][m]
// ---------------------------------------------------------------------------
__global__ void combine_kernel(const float* __restrict__ op, float* __restrict__ out) {
    int m = blockIdx.x, b = blockIdx.y, d = threadIdx.x;
    size_t src = ((size_t)b * MP + m) * DD + d;
    float v = op[src] + op[src + (size_t)8 * MP * DD];
    out[((size_t)b * NQ + m) * DD + d] = v;
    if (m >= 1 && m <= 1023)
        out[((size_t)b * NQ + 2048 - m) * DD + d] = v;
}

// ---------------------------------------------------------------------------
extern "C" void kernel_launch(void* const* d_in, const int* in_sizes, int n_in,
                              void* d_out, int out_size) {
    const float* query = (const float*)d_in[0];
    const float* key   = (const float*)d_in[1];
    const float* Wq    = (const float*)d_in[2];
    const float* bq    = (const float*)d_in[3];
    const float* Wk    = (const float*)d_in[4];
    const float* bk    = (const float*)d_in[5];
    float* out = (float*)d_out;

#define SYM(p, s) void* p; cudaGetSymbolAddress(&p, s)
    SYM(qH, g_qH);   SYM(qL, g_qL);   SYM(kH, g_kH);   SYM(kL, g_kL);
    SYM(wqH, g_wqH); SYM(wqL, g_wqL); SYM(wkH, g_wkH); SYM(wkL, g_wkL);
    SYM(qpTH, g_qpTH); SYM(qpTL, g_qpTL);
    SYM(qpFH, g_qpFH); SYM(qpFL, g_qpFL);
    SYM(kpH, g_kpH); SYM(kpL, g_kpL);
    SYM(qfH, g_qfH); SYM(qfL, g_qfL);
    SYM(vTH, g_vTH); SYM(vTL, g_vTL);
    SYM(pH, g_pH);   SYM(pL, g_pL);
    SYM(CH, g_CH);   SYM(CL, g_CL);
    SYM(sc, g_scores); SYM(op, g_op);
#undef SYM

    cudaFuncSetAttribute((const void*)gemm_kernel<1,0>, cudaFuncAttributeMaxDynamicSharedMemorySize, SM_BYTES);
    cudaFuncSetAttribute((const void*)gemm_kernel<0,0>, cudaFuncAttributeMaxDynamicSharedMemorySize, SM_BYTES);
    cudaFuncSetAttribute((const void*)gemm_kernel<0,1>, cudaFuncAttributeMaxDynamicSharedMemorySize, SM_BYTES);

    // preps
    cinit_kernel<<<(MP * 1024 + 255) / 256, 256>>>();
    split_kernel<<<16384, 256>>>(query, (bf16*)qH, (bf16*)qL, BB * NQ * DD);
    split_kernel<<<16384, 256>>>(key,   (bf16*)kH, (bf16*)kL, BB * NK * DD);
    split_kernel<<<256, 256>>>(Wq, (bf16*)wqH, (bf16*)wqL, DD * DD);
    split_kernel<<<256, 256>>>(Wk, (bf16*)wkH, (bf16*)wkL, DD * DD);
    transpose_kernel<<<dim3(NK / 32, DD / 32, BB), dim3(32, 8)>>>(
        key, (bf16*)vTH, (bf16*)vTL);

    // G1: qprojT[d, b*m] = Wq @ query^T    (M=256, N=16384, K=256)
    gemm_kernel<1,0><<<dim3(64, 2, 1), 512, SM_BYTES>>>(
        (bf16*)wqH, (bf16*)wqL, 0, DD, (bf16*)qH, (bf16*)qL, 0, DD,
        nullptr, nullptr, (bf16*)qpTH, (bf16*)qpTL, 0, BB * NQ, DD);
    // G2: kproj = key @ Wk^T + bk          (M=16384, N=256, K=256)
    gemm_kernel<1,0><<<dim3(1, 128, 1), 512, SM_BYTES>>>(
        (bf16*)kH, (bf16*)kL, 0, DD, (bf16*)wkH, (bf16*)wkL, 0, DD,
        bk, nullptr, (bf16*)kpH, (bf16*)kpL, 0, DD, DD);

    // fold + row-1024 extraction (after G1)
    fold_kernel<<<(DD * BB * 1024 + 255) / 256, 256>>>();
    q1024_kernel<<<(BB * DD + 255) / 256, 256>>>();

    // G3: qfft partials = Cfold @ qpF^T, 2-way split-K (per bz: M=1152, N=256, K=512)
    gemm_kernel<0,1><<<dim3(1, 9, 16), 512, SM_BYTES>>>(
        (bf16*)CH, (bf16*)CL, 0, 1024, (bf16*)qpFH, (bf16*)qpFL, 1024, BB * 1024,
        nullptr, (float*)op, nullptr, nullptr, (size_t)MP * DD, DD, 512);
    // combine G3 partials + bq + (-1)^m q1024 -> qf hi/lo
    g3combine_kernel<<<dim3(MP, BB), 256>>>((const float*)op, bq);

    // G4: scores = qfft @ kproj^T          (per b: M=1152, N=2048, K=256)
    gemm_kernel<0,0><<<dim3(8, 9, BB), 512, SM_BYTES>>>(
        (bf16*)qfH, (bf16*)qfL, (size_t)MP * DD, DD,
        (bf16*)kpH, (bf16*)kpL, (size_t)NK * DD, DD,
        nullptr, (float*)sc, nullptr, nullptr, (size_t)MP * NK, NK, DD);
    // softmax -> probs hi/lo
    softmax_kernel<<<BB * MP, 256>>>((float*)sc, (bf16*)pH, (bf16*)pL);
    // G5: partial out = probs @ vT^T, 2-way split-K  (per bz: M=1152, N=256, K=1024)
    gemm_kernel<0,1><<<dim3(1, 9, 16), 512, SM_BYTES>>>(
        (bf16*)pH, (bf16*)pL, (size_t)MP * NK, NK,
        (bf16*)vTH, (bf16*)vTL, (size_t)DD * NK, NK,
        nullptr, (float*)op, nullptr, nullptr, (size_t)MP * DD, DD, 1024);
    // combine partials + mirror
    combine_kernel<<<dim3(1025, BB), 256>>>((const float*)op, out);
}